// round 10
// baseline (speedup 1.0000x reference)
#include <cuda_runtime.h>
#include <math.h>

#define Bq   128
#define Lq   256
#define Dq   512
#define Hq   1024
#define Oq   2
#define NCTA 128   // persistent recurrence grid

// ---------------- scratch (static device allocations; no cudaMalloc) --------
__device__ float g_xp[(size_t)Lq * Bq * Hq];   // (L, B, H)  128 MB
__device__ float g_hs[(size_t)Lq * Bq * Hq];   // (L, B, H)  128 MB
__device__ float g_zp[4 * Bq * Hq];            // split-K partials, 2 MB
__device__ unsigned g_count;
__device__ unsigned g_phase;

// ---------------- barrier init (reset every launch for graph replay) --------
__global__ void init_bar_kernel() {
    g_count = 0u;
    g_phase = 0u;
}

// ---------------- software grid barrier (all NCTA CTAs co-resident) ---------
__device__ __forceinline__ void gsync(unsigned &target) {
    __threadfence();          // make this thread's global writes visible
    __syncthreads();
    if (threadIdx.x == 0) {
        unsigned a = atomicAdd(&g_count, 1u);
        if (a == NCTA - 1) {
            g_count = 0u;
            __threadfence();
            atomicAdd(&g_phase, 1u);
        } else {
            while (*((volatile unsigned *)&g_phase) <= target) { /* spin */ }
        }
    }
    __syncthreads();
    target++;
}

// ---------------- xp = reshape(x) @ Wx + bx ---------------------------------
// Output row m = l*B + b  (time-major), A row = x[b][l][:]
// 64x64 tile, 4x4 micro-tile, 256 threads, KT=16.
__global__ __launch_bounds__(256) void xp_gemm_kernel(
        const float* __restrict__ x,
        const float* __restrict__ Wx,
        const float* __restrict__ bx) {
    __shared__ float aS[64][16];
    __shared__ float wS[16][64];

    const int tid = threadIdx.x;
    const int tx = tid & 15;        // j direction (4 cols each)
    const int ty = tid >> 4;        // m direction (4 rows each)
    const int m0 = blockIdx.y * 64;
    const int n0 = blockIdx.x * 64;

    // loader roles
    const int abb  = tid >> 2;            // 0..63  (row in tile)
    const int akk4 = (tid & 3) * 4;       // 0,4,8,12
    const int wkk  = tid >> 4;            // 0..15
    const int wjj  = (tid & 15) * 4;      // 0..60

    const int m = m0 + abb;
    // x is (B, L, D): offset of row m: b = m%128, l = m/128
    const float* arow = x + ((size_t)(m & (Bq - 1)) * Lq + (m >> 7)) * Dq;

    float acc[4][4] = {};

    for (int k0 = 0; k0 < Dq; k0 += 16) {
        float4 av = *(const float4*)(arow + k0 + akk4);
        *(float4*)&aS[abb][akk4] = av;
        float4 wv = *(const float4*)(Wx + (size_t)(k0 + wkk) * Hq + n0 + wjj);
        *(float4*)&wS[wkk][wjj] = wv;
        __syncthreads();
#pragma unroll
        for (int kk = 0; kk < 16; kk++) {
            float4 w4 = *(float4*)&wS[kk][tx * 4];
            float av4[4];
#pragma unroll
            for (int i = 0; i < 4; i++) av4[i] = aS[ty * 4 + i][kk];
#pragma unroll
            for (int i = 0; i < 4; i++) {
                acc[i][0] += av4[i] * w4.x;
                acc[i][1] += av4[i] * w4.y;
                acc[i][2] += av4[i] * w4.z;
                acc[i][3] += av4[i] * w4.w;
            }
        }
        __syncthreads();
    }

    const int j = n0 + tx * 4;
    float4 bxv = *(const float4*)(bx + j);
#pragma unroll
    for (int i = 0; i < 4; i++) {
        int mm = m0 + ty * 4 + i;
        float4 o;
        o.x = acc[i][0] + bxv.x;
        o.y = acc[i][1] + bxv.y;
        o.z = acc[i][2] + bxv.z;
        o.w = acc[i][3] + bxv.w;
        *(float4*)(g_xp + (size_t)mm * Hq + j) = o;
    }
}

// ---------------- persistent recurrence kernel ------------------------------
// 128 CTAs x 256 threads.
// Phase A (l>0): split-K GEMM partials  z_part = h[l-1] @ Wh
//   CTA (ks, bt, jt): b-tile 64, j-tile 64, k-range 256. 4x4 micro-tiles.
// Phase B: CTA c owns b-row c (1024 j). thread owns j = tid*4..+3, c in regs.
__global__ __launch_bounds__(256) void rnn_persist_kernel(
        const float* __restrict__ Wh,
        const float* __restrict__ bh) {
    const int tid = threadIdx.x;
    const int cta = blockIdx.x;
    const int ks  = cta >> 5;            // 0..3
    const int rem = cta & 31;
    const int bt  = rem >> 4;            // 0..1
    const int jt  = rem & 15;            // 0..15
    const int b0  = bt * 64;
    const int j0  = jt * 64;
    const int kbase = ks * 256;

    const int tx = tid & 15;
    const int ty = tid >> 4;

    __shared__ float hS[64][16];
    __shared__ float wS[16][64];

    // loader roles (phase A)
    const int hbb  = tid >> 2;
    const int hkk4 = (tid & 3) * 4;
    const int wkk  = tid >> 4;
    const int wjj  = (tid & 15) * 4;

    // phase B ownership: element range e0..e0+3 of the (B*H) state
    const size_t e0 = ((size_t)cta * 256 + tid) * 4;   // b = cta, j = tid*4
    float4 bhv = *(const float4*)(bh + (tid * 4));
    float c0 = 0.f, c1 = 0.f, c2 = 0.f, c3 = 0.f;

    unsigned target = 0;

    for (int l = 0; l < Lq; l++) {
        float zs0 = 0.f, zs1 = 0.f, zs2 = 0.f, zs3 = 0.f;
        if (l > 0) {
            // ---------------- phase A ----------------
            float acc[4][4] = {};
            const float* hprev = g_hs + (size_t)(l - 1) * Bq * Hq;
            for (int kc = 0; kc < 256; kc += 16) {
                const int k0 = kbase + kc;
                float4 hv = __ldcg((const float4*)(hprev +
                                   (size_t)(b0 + hbb) * Hq + k0 + hkk4));
                *(float4*)&hS[hbb][hkk4] = hv;
                float4 wv = *(const float4*)(Wh +
                                   (size_t)(k0 + wkk) * Hq + j0 + wjj);
                *(float4*)&wS[wkk][wjj] = wv;
                __syncthreads();
#pragma unroll
                for (int kk = 0; kk < 16; kk++) {
                    float4 w4 = *(float4*)&wS[kk][tx * 4];
                    float av4[4];
#pragma unroll
                    for (int i = 0; i < 4; i++) av4[i] = hS[ty * 4 + i][kk];
#pragma unroll
                    for (int i = 0; i < 4; i++) {
                        acc[i][0] += av4[i] * w4.x;
                        acc[i][1] += av4[i] * w4.y;
                        acc[i][2] += av4[i] * w4.z;
                        acc[i][3] += av4[i] * w4.w;
                    }
                }
                __syncthreads();
            }
            // write partials
            float* zp = g_zp + (size_t)ks * Bq * Hq;
#pragma unroll
            for (int i = 0; i < 4; i++) {
                float4 o = make_float4(acc[i][0], acc[i][1], acc[i][2], acc[i][3]);
                *(float4*)(zp + (size_t)(b0 + ty * 4 + i) * Hq + j0 + tx * 4) = o;
            }
            gsync(target);   // partials visible to everyone

            // ---------------- phase B: reduce partials ----------------
            float4 p0 = __ldcg((const float4*)(g_zp + e0));
            float4 p1 = __ldcg((const float4*)(g_zp + (size_t)Bq * Hq + e0));
            float4 p2 = __ldcg((const float4*)(g_zp + (size_t)2 * Bq * Hq + e0));
            float4 p3 = __ldcg((const float4*)(g_zp + (size_t)3 * Bq * Hq + e0));
            zs0 = p0.x + p1.x + p2.x + p3.x;
            zs1 = p0.y + p1.y + p2.y + p3.y;
            zs2 = p0.z + p1.z + p2.z + p3.z;
            zs3 = p0.w + p1.w + p2.w + p3.w;
        }

        float4 xpv = __ldcg((const float4*)(g_xp + (size_t)l * Bq * Hq + e0));
        float z0 = zs0 + bhv.x + xpv.x;
        float z1 = zs1 + bhv.y + xpv.y;
        float z2 = zs2 + bhv.z + xpv.z;
        float z3 = zs3 + bhv.w + xpv.w;

        float sg0 = 1.f / (1.f + expf(-z0));
        float sg1 = 1.f / (1.f + expf(-z1));
        float sg2 = 1.f / (1.f + expf(-z2));
        float sg3 = 1.f / (1.f + expf(-z3));
        float g0 = tanhf(z0), g1 = tanhf(z1), g2 = tanhf(z2), g3 = tanhf(z3);
        c0 = sg0 * (c0 + g0);
        c1 = sg1 * (c1 + g1);
        c2 = sg2 * (c2 + g2);
        c3 = sg3 * (c3 + g3);
        float4 hv;
        hv.x = sg0 * tanhf(c0);
        hv.y = sg1 * tanhf(c1);
        hv.z = sg2 * tanhf(c2);
        hv.w = sg3 * tanhf(c3);
        *(float4*)(g_hs + (size_t)l * Bq * Hq + e0) = hv;

        gsync(target);   // h[l] visible before next phase A
    }
}

// ---------------- output projection + masking -------------------------------
// One warp per (b,l) output row. out row index = b*L + l.
__global__ __launch_bounds__(256) void out_kernel(
        const float* __restrict__ Wo,
        const float* __restrict__ bo,
        const int*   __restrict__ slen,
        float*       __restrict__ out) {
    __shared__ float woS[Hq * Oq];
    const int tid = threadIdx.x;
    for (int i = tid; i < Hq * Oq; i += 256) woS[i] = Wo[i];
    __syncthreads();

    const int warp = blockIdx.x * 8 + (tid >> 5);
    const int lane = tid & 31;
    const int b = warp >> 8;      // / L
    const int l = warp & (Lq - 1);

    const float* hrow = g_hs + ((size_t)l * Bq + b) * Hq;
    float a0 = 0.f, a1 = 0.f;
    for (int j = lane; j < Hq; j += 32) {
        float h = hrow[j];
        a0 += h * woS[j * 2];
        a1 += h * woS[j * 2 + 1];
    }
#pragma unroll
    for (int off = 16; off; off >>= 1) {
        a0 += __shfl_xor_sync(0xffffffffu, a0, off);
        a1 += __shfl_xor_sync(0xffffffffu, a1, off);
    }
    if (lane == 0) {
        float o0, o1;
        if (l <= slen[b]) {
            o0 = 1.f / (1.f + expf(-(a0 + bo[0])));
            o1 = 1.f / (1.f + expf(-(a1 + bo[1])));
        } else {
            o0 = 0.f;
            o1 = 1.f;
        }
        out[(size_t)warp * 2]     = o0;
        out[(size_t)warp * 2 + 1] = o1;
    }
}

// ---------------- launch ----------------------------------------------------
extern "C" void kernel_launch(void* const* d_in, const int* in_sizes, int n_in,
                              void* d_out, int out_size) {
    const float* x    = (const float*)d_in[0];
    const int*   slen = (const int*)  d_in[1];
    const float* Wh   = (const float*)d_in[2];
    const float* bh   = (const float*)d_in[3];
    const float* Wx   = (const float*)d_in[4];
    const float* bx   = (const float*)d_in[5];
    const float* Wo   = (const float*)d_in[6];
    const float* bo   = (const float*)d_in[7];
    float* out = (float*)d_out;

    init_bar_kernel<<<1, 1>>>();

    dim3 g1(Hq / 64, (Bq * Lq) / 64);       // (16, 512)
    xp_gemm_kernel<<<g1, 256>>>(x, Wx, bx);

    rnn_persist_kernel<<<NCTA, 256>>>(Wh, bh);

    out_kernel<<<(Bq * Lq) / 8, 256>>>(Wo, bo, slen, out);
}

// round 11
// speedup vs baseline: 1.0007x; 1.0007x over previous
#include <cuda_runtime.h>
#include <math.h>

#define Bq   128
#define Lq   256
#define Dq   512
#define Hq   1024
#define Oq   2
#define NCTA 128   // persistent recurrence grid

// ---------------- scratch (static device allocations; no cudaMalloc) --------
__device__ float g_xp[(size_t)Lq * Bq * Hq];   // (L, B, H)  128 MB
__device__ float g_hs[(size_t)Lq * Bq * Hq];   // (L, B, H)  128 MB
__device__ float g_zp[4 * Bq * Hq];            // split-K partials, 2 MB
__device__ unsigned g_count;
__device__ unsigned g_phase;

// ---------------- barrier init (reset every launch for graph replay) --------
__global__ void init_bar_kernel() {
    g_count = 0u;
    g_phase = 0u;
}

// ---------------- software grid barrier (all NCTA CTAs co-resident) ---------
__device__ __forceinline__ void gsync(unsigned &target) {
    __threadfence();          // make this thread's global writes visible
    __syncthreads();
    if (threadIdx.x == 0) {
        unsigned a = atomicAdd(&g_count, 1u);
        if (a == NCTA - 1) {
            g_count = 0u;
            __threadfence();
            atomicAdd(&g_phase, 1u);
        } else {
            while (*((volatile unsigned *)&g_phase) <= target) { /* spin */ }
        }
    }
    __syncthreads();
    target++;
}

// ---------------- xp = reshape(x) @ Wx + bx ---------------------------------
// Output row m = l*B + b  (time-major), A row = x[b][l][:]
// 64x64 tile, 4x4 micro-tile, 256 threads, KT=16.
__global__ __launch_bounds__(256) void xp_gemm_kernel(
        const float* __restrict__ x,
        const float* __restrict__ Wx,
        const float* __restrict__ bx) {
    __shared__ float aS[64][16];
    __shared__ float wS[16][64];

    const int tid = threadIdx.x;
    const int tx = tid & 15;        // j direction (4 cols each)
    const int ty = tid >> 4;        // m direction (4 rows each)
    const int m0 = blockIdx.y * 64;
    const int n0 = blockIdx.x * 64;

    // loader roles
    const int abb  = tid >> 2;            // 0..63  (row in tile)
    const int akk4 = (tid & 3) * 4;       // 0,4,8,12
    const int wkk  = tid >> 4;            // 0..15
    const int wjj  = (tid & 15) * 4;      // 0..60

    const int m = m0 + abb;
    // x is (B, L, D): offset of row m: b = m%128, l = m/128
    const float* arow = x + ((size_t)(m & (Bq - 1)) * Lq + (m >> 7)) * Dq;

    float acc[4][4] = {};

    for (int k0 = 0; k0 < Dq; k0 += 16) {
        float4 av = *(const float4*)(arow + k0 + akk4);
        *(float4*)&aS[abb][akk4] = av;
        float4 wv = *(const float4*)(Wx + (size_t)(k0 + wkk) * Hq + n0 + wjj);
        *(float4*)&wS[wkk][wjj] = wv;
        __syncthreads();
#pragma unroll
        for (int kk = 0; kk < 16; kk++) {
            float4 w4 = *(float4*)&wS[kk][tx * 4];
            float av4[4];
#pragma unroll
            for (int i = 0; i < 4; i++) av4[i] = aS[ty * 4 + i][kk];
#pragma unroll
            for (int i = 0; i < 4; i++) {
                acc[i][0] += av4[i] * w4.x;
                acc[i][1] += av4[i] * w4.y;
                acc[i][2] += av4[i] * w4.z;
                acc[i][3] += av4[i] * w4.w;
            }
        }
        __syncthreads();
    }

    const int j = n0 + tx * 4;
    float4 bxv = *(const float4*)(bx + j);
#pragma unroll
    for (int i = 0; i < 4; i++) {
        int mm = m0 + ty * 4 + i;
        float4 o;
        o.x = acc[i][0] + bxv.x;
        o.y = acc[i][1] + bxv.y;
        o.z = acc[i][2] + bxv.z;
        o.w = acc[i][3] + bxv.w;
        *(float4*)(g_xp + (size_t)mm * Hq + j) = o;
    }
}

// ---------------- persistent recurrence kernel ------------------------------
// 128 CTAs x 256 threads.
// Phase A (l>0): split-K GEMM partials  z_part = h[l-1] @ Wh
//   CTA (ks, bt, jt): b-tile 64, j-tile 64, k-range 256. 4x4 micro-tiles.
// Phase B: CTA c owns b-row c (1024 j). thread owns j = tid*4..+3, c in regs.
__global__ __launch_bounds__(256) void rnn_persist_kernel(
        const float* __restrict__ Wh,
        const float* __restrict__ bh) {
    const int tid = threadIdx.x;
    const int cta = blockIdx.x;
    const int ks  = cta >> 5;            // 0..3
    const int rem = cta & 31;
    const int bt  = rem >> 4;            // 0..1
    const int jt  = rem & 15;            // 0..15
    const int b0  = bt * 64;
    const int j0  = jt * 64;
    const int kbase = ks * 256;

    const int tx = tid & 15;
    const int ty = tid >> 4;

    __shared__ float hS[64][16];
    __shared__ float wS[16][64];

    // loader roles (phase A)
    const int hbb  = tid >> 2;
    const int hkk4 = (tid & 3) * 4;
    const int wkk  = tid >> 4;
    const int wjj  = (tid & 15) * 4;

    // phase B ownership: element range e0..e0+3 of the (B*H) state
    const size_t e0 = ((size_t)cta * 256 + tid) * 4;   // b = cta, j = tid*4
    float4 bhv = *(const float4*)(bh + (tid * 4));
    float c0 = 0.f, c1 = 0.f, c2 = 0.f, c3 = 0.f;

    unsigned target = 0;

    for (int l = 0; l < Lq; l++) {
        float zs0 = 0.f, zs1 = 0.f, zs2 = 0.f, zs3 = 0.f;
        if (l > 0) {
            // ---------------- phase A ----------------
            float acc[4][4] = {};
            const float* hprev = g_hs + (size_t)(l - 1) * Bq * Hq;
            for (int kc = 0; kc < 256; kc += 16) {
                const int k0 = kbase + kc;
                float4 hv = __ldcg((const float4*)(hprev +
                                   (size_t)(b0 + hbb) * Hq + k0 + hkk4));
                *(float4*)&hS[hbb][hkk4] = hv;
                float4 wv = *(const float4*)(Wh +
                                   (size_t)(k0 + wkk) * Hq + j0 + wjj);
                *(float4*)&wS[wkk][wjj] = wv;
                __syncthreads();
#pragma unroll
                for (int kk = 0; kk < 16; kk++) {
                    float4 w4 = *(float4*)&wS[kk][tx * 4];
                    float av4[4];
#pragma unroll
                    for (int i = 0; i < 4; i++) av4[i] = hS[ty * 4 + i][kk];
#pragma unroll
                    for (int i = 0; i < 4; i++) {
                        acc[i][0] += av4[i] * w4.x;
                        acc[i][1] += av4[i] * w4.y;
                        acc[i][2] += av4[i] * w4.z;
                        acc[i][3] += av4[i] * w4.w;
                    }
                }
                __syncthreads();
            }
            // write partials
            float* zp = g_zp + (size_t)ks * Bq * Hq;
#pragma unroll
            for (int i = 0; i < 4; i++) {
                float4 o = make_float4(acc[i][0], acc[i][1], acc[i][2], acc[i][3]);
                *(float4*)(zp + (size_t)(b0 + ty * 4 + i) * Hq + j0 + tx * 4) = o;
            }
            gsync(target);   // partials visible to everyone

            // ---------------- phase B: reduce partials ----------------
            float4 p0 = __ldcg((const float4*)(g_zp + e0));
            float4 p1 = __ldcg((const float4*)(g_zp + (size_t)Bq * Hq + e0));
            float4 p2 = __ldcg((const float4*)(g_zp + (size_t)2 * Bq * Hq + e0));
            float4 p3 = __ldcg((const float4*)(g_zp + (size_t)3 * Bq * Hq + e0));
            zs0 = p0.x + p1.x + p2.x + p3.x;
            zs1 = p0.y + p1.y + p2.y + p3.y;
            zs2 = p0.z + p1.z + p2.z + p3.z;
            zs3 = p0.w + p1.w + p2.w + p3.w;
        }

        float4 xpv = __ldcg((const float4*)(g_xp + (size_t)l * Bq * Hq + e0));
        float z0 = zs0 + bhv.x + xpv.x;
        float z1 = zs1 + bhv.y + xpv.y;
        float z2 = zs2 + bhv.z + xpv.z;
        float z3 = zs3 + bhv.w + xpv.w;

        float sg0 = 1.f / (1.f + expf(-z0));
        float sg1 = 1.f / (1.f + expf(-z1));
        float sg2 = 1.f / (1.f + expf(-z2));
        float sg3 = 1.f / (1.f + expf(-z3));
        float g0 = tanhf(z0), g1 = tanhf(z1), g2 = tanhf(z2), g3 = tanhf(z3);
        c0 = sg0 * (c0 + g0);
        c1 = sg1 * (c1 + g1);
        c2 = sg2 * (c2 + g2);
        c3 = sg3 * (c3 + g3);
        float4 hv;
        hv.x = sg0 * tanhf(c0);
        hv.y = sg1 * tanhf(c1);
        hv.z = sg2 * tanhf(c2);
        hv.w = sg3 * tanhf(c3);
        *(float4*)(g_hs + (size_t)l * Bq * Hq + e0) = hv;

        gsync(target);   // h[l] visible before next phase A
    }
}

// ---------------- output projection + masking -------------------------------
// One warp per (b,l) output row. out row index = b*L + l.
__global__ __launch_bounds__(256) void out_kernel(
        const float* __restrict__ Wo,
        const float* __restrict__ bo,
        const int*   __restrict__ slen,
        float*       __restrict__ out) {
    __shared__ float woS[Hq * Oq];
    const int tid = threadIdx.x;
    for (int i = tid; i < Hq * Oq; i += 256) woS[i] = Wo[i];
    __syncthreads();

    const int warp = blockIdx.x * 8 + (tid >> 5);
    const int lane = tid & 31;
    const int b = warp >> 8;      // / L
    const int l = warp & (Lq - 1);

    const float* hrow = g_hs + ((size_t)l * Bq + b) * Hq;
    float a0 = 0.f, a1 = 0.f;
    for (int j = lane; j < Hq; j += 32) {
        float h = hrow[j];
        a0 += h * woS[j * 2];
        a1 += h * woS[j * 2 + 1];
    }
#pragma unroll
    for (int off = 16; off; off >>= 1) {
        a0 += __shfl_xor_sync(0xffffffffu, a0, off);
        a1 += __shfl_xor_sync(0xffffffffu, a1, off);
    }
    if (lane == 0) {
        float o0, o1;
        if (l <= slen[b]) {
            o0 = 1.f / (1.f + expf(-(a0 + bo[0])));
            o1 = 1.f / (1.f + expf(-(a1 + bo[1])));
        } else {
            o0 = 0.f;
            o1 = 1.f;
        }
        out[(size_t)warp * 2]     = o0;
        out[(size_t)warp * 2 + 1] = o1;
    }
}

// ---------------- launch ----------------------------------------------------
extern "C" void kernel_launch(void* const* d_in, const int* in_sizes, int n_in,
                              void* d_out, int out_size) {
    const float* x    = (const float*)d_in[0];
    const int*   slen = (const int*)  d_in[1];
    const float* Wh   = (const float*)d_in[2];
    const float* bh   = (const float*)d_in[3];
    const float* Wx   = (const float*)d_in[4];
    const float* bx   = (const float*)d_in[5];
    const float* Wo   = (const float*)d_in[6];
    const float* bo   = (const float*)d_in[7];
    float* out = (float*)d_out;

    init_bar_kernel<<<1, 1>>>();

    dim3 g1(Hq / 64, (Bq * Lq) / 64);       // (16, 512)
    xp_gemm_kernel<<<g1, 256>>>(x, Wx, bx);

    rnn_persist_kernel<<<NCTA, 256>>>(Wh, bh);

    out_kernel<<<(Bq * Lq) / 8, 256>>>(Wo, bo, slen, out);
}

// round 12
// speedup vs baseline: 1.0034x; 1.0027x over previous
#include <cuda_runtime.h>
#include <math.h>

#define Bq   128
#define Lq   256
#define Dq   512
#define Hq   1024
#define Oq   2
#define NCTA 128   // persistent recurrence grid

// ---------------- scratch (static device allocations; no cudaMalloc) --------
__device__ float g_xp[(size_t)Lq * Bq * Hq];   // (L, B, H)  128 MB
__device__ float g_hs[(size_t)Lq * Bq * Hq];   // (L, B, H)  128 MB
__device__ float g_zp[4 * Bq * Hq];            // split-K partials, 2 MB
__device__ unsigned g_count;
__device__ unsigned g_phase;

// ---------------- barrier init (reset every launch for graph replay) --------
__global__ void init_bar_kernel() {
    g_count = 0u;
    g_phase = 0u;
}

// ---------------- software grid barrier (all NCTA CTAs co-resident) ---------
__device__ __forceinline__ void gsync(unsigned &target) {
    __threadfence();          // make this thread's global writes visible
    __syncthreads();
    if (threadIdx.x == 0) {
        unsigned a = atomicAdd(&g_count, 1u);
        if (a == NCTA - 1) {
            g_count = 0u;
            __threadfence();
            atomicAdd(&g_phase, 1u);
        } else {
            while (*((volatile unsigned *)&g_phase) <= target) { /* spin */ }
        }
    }
    __syncthreads();
    target++;
}

// ---------------- xp = reshape(x) @ Wx + bx ---------------------------------
// Output row m = l*B + b  (time-major), A row = x[b][l][:]
// 64x64 tile, 4x4 micro-tile, 256 threads, KT=16.
__global__ __launch_bounds__(256) void xp_gemm_kernel(
        const float* __restrict__ x,
        const float* __restrict__ Wx,
        const float* __restrict__ bx) {
    __shared__ float aS[64][16];
    __shared__ float wS[16][64];

    const int tid = threadIdx.x;
    const int tx = tid & 15;        // j direction (4 cols each)
    const int ty = tid >> 4;        // m direction (4 rows each)
    const int m0 = blockIdx.y * 64;
    const int n0 = blockIdx.x * 64;

    // loader roles
    const int abb  = tid >> 2;            // 0..63  (row in tile)
    const int akk4 = (tid & 3) * 4;       // 0,4,8,12
    const int wkk  = tid >> 4;            // 0..15
    const int wjj  = (tid & 15) * 4;      // 0..60

    const int m = m0 + abb;
    // x is (B, L, D): offset of row m: b = m%128, l = m/128
    const float* arow = x + ((size_t)(m & (Bq - 1)) * Lq + (m >> 7)) * Dq;

    float acc[4][4] = {};

    for (int k0 = 0; k0 < Dq; k0 += 16) {
        float4 av = *(const float4*)(arow + k0 + akk4);
        *(float4*)&aS[abb][akk4] = av;
        float4 wv = *(const float4*)(Wx + (size_t)(k0 + wkk) * Hq + n0 + wjj);
        *(float4*)&wS[wkk][wjj] = wv;
        __syncthreads();
#pragma unroll
        for (int kk = 0; kk < 16; kk++) {
            float4 w4 = *(float4*)&wS[kk][tx * 4];
            float av4[4];
#pragma unroll
            for (int i = 0; i < 4; i++) av4[i] = aS[ty * 4 + i][kk];
#pragma unroll
            for (int i = 0; i < 4; i++) {
                acc[i][0] += av4[i] * w4.x;
                acc[i][1] += av4[i] * w4.y;
                acc[i][2] += av4[i] * w4.z;
                acc[i][3] += av4[i] * w4.w;
            }
        }
        __syncthreads();
    }

    const int j = n0 + tx * 4;
    float4 bxv = *(const float4*)(bx + j);
#pragma unroll
    for (int i = 0; i < 4; i++) {
        int mm = m0 + ty * 4 + i;
        float4 o;
        o.x = acc[i][0] + bxv.x;
        o.y = acc[i][1] + bxv.y;
        o.z = acc[i][2] + bxv.z;
        o.w = acc[i][3] + bxv.w;
        *(float4*)(g_xp + (size_t)mm * Hq + j) = o;
    }
}

// ---------------- persistent recurrence kernel ------------------------------
// 128 CTAs x 256 threads.
// Phase A (l>0): split-K GEMM partials  z_part = h[l-1] @ Wh
//   CTA (ks, bt, jt): b-tile 64, j-tile 64, k-range 256. 4x4 micro-tiles.
// Phase B: CTA c owns b-row c (1024 j). thread owns j = tid*4..+3, c in regs.
__global__ __launch_bounds__(256) void rnn_persist_kernel(
        const float* __restrict__ Wh,
        const float* __restrict__ bh) {
    const int tid = threadIdx.x;
    const int cta = blockIdx.x;
    const int ks  = cta >> 5;            // 0..3
    const int rem = cta & 31;
    const int bt  = rem >> 4;            // 0..1
    const int jt  = rem & 15;            // 0..15
    const int b0  = bt * 64;
    const int j0  = jt * 64;
    const int kbase = ks * 256;

    const int tx = tid & 15;
    const int ty = tid >> 4;

    __shared__ float hS[64][16];
    __shared__ float wS[16][64];

    // loader roles (phase A)
    const int hbb  = tid >> 2;
    const int hkk4 = (tid & 3) * 4;
    const int wkk  = tid >> 4;
    const int wjj  = (tid & 15) * 4;

    // phase B ownership: element range e0..e0+3 of the (B*H) state
    const size_t e0 = ((size_t)cta * 256 + tid) * 4;   // b = cta, j = tid*4
    float4 bhv = *(const float4*)(bh + (tid * 4));
    float c0 = 0.f, c1 = 0.f, c2 = 0.f, c3 = 0.f;

    unsigned target = 0;

    for (int l = 0; l < Lq; l++) {
        float zs0 = 0.f, zs1 = 0.f, zs2 = 0.f, zs3 = 0.f;
        if (l > 0) {
            // ---------------- phase A ----------------
            float acc[4][4] = {};
            const float* hprev = g_hs + (size_t)(l - 1) * Bq * Hq;
            for (int kc = 0; kc < 256; kc += 16) {
                const int k0 = kbase + kc;
                float4 hv = __ldcg((const float4*)(hprev +
                                   (size_t)(b0 + hbb) * Hq + k0 + hkk4));
                *(float4*)&hS[hbb][hkk4] = hv;
                float4 wv = *(const float4*)(Wh +
                                   (size_t)(k0 + wkk) * Hq + j0 + wjj);
                *(float4*)&wS[wkk][wjj] = wv;
                __syncthreads();
#pragma unroll
                for (int kk = 0; kk < 16; kk++) {
                    float4 w4 = *(float4*)&wS[kk][tx * 4];
                    float av4[4];
#pragma unroll
                    for (int i = 0; i < 4; i++) av4[i] = hS[ty * 4 + i][kk];
#pragma unroll
                    for (int i = 0; i < 4; i++) {
                        acc[i][0] += av4[i] * w4.x;
                        acc[i][1] += av4[i] * w4.y;
                        acc[i][2] += av4[i] * w4.z;
                        acc[i][3] += av4[i] * w4.w;
                    }
                }
                __syncthreads();
            }
            // write partials
            float* zp = g_zp + (size_t)ks * Bq * Hq;
#pragma unroll
            for (int i = 0; i < 4; i++) {
                float4 o = make_float4(acc[i][0], acc[i][1], acc[i][2], acc[i][3]);
                *(float4*)(zp + (size_t)(b0 + ty * 4 + i) * Hq + j0 + tx * 4) = o;
            }
            gsync(target);   // partials visible to everyone

            // ---------------- phase B: reduce partials ----------------
            float4 p0 = __ldcg((const float4*)(g_zp + e0));
            float4 p1 = __ldcg((const float4*)(g_zp + (size_t)Bq * Hq + e0));
            float4 p2 = __ldcg((const float4*)(g_zp + (size_t)2 * Bq * Hq + e0));
            float4 p3 = __ldcg((const float4*)(g_zp + (size_t)3 * Bq * Hq + e0));
            zs0 = p0.x + p1.x + p2.x + p3.x;
            zs1 = p0.y + p1.y + p2.y + p3.y;
            zs2 = p0.z + p1.z + p2.z + p3.z;
            zs3 = p0.w + p1.w + p2.w + p3.w;
        }

        float4 xpv = __ldcg((const float4*)(g_xp + (size_t)l * Bq * Hq + e0));
        float z0 = zs0 + bhv.x + xpv.x;
        float z1 = zs1 + bhv.y + xpv.y;
        float z2 = zs2 + bhv.z + xpv.z;
        float z3 = zs3 + bhv.w + xpv.w;

        float sg0 = 1.f / (1.f + expf(-z0));
        float sg1 = 1.f / (1.f + expf(-z1));
        float sg2 = 1.f / (1.f + expf(-z2));
        float sg3 = 1.f / (1.f + expf(-z3));
        float g0 = tanhf(z0), g1 = tanhf(z1), g2 = tanhf(z2), g3 = tanhf(z3);
        c0 = sg0 * (c0 + g0);
        c1 = sg1 * (c1 + g1);
        c2 = sg2 * (c2 + g2);
        c3 = sg3 * (c3 + g3);
        float4 hv;
        hv.x = sg0 * tanhf(c0);
        hv.y = sg1 * tanhf(c1);
        hv.z = sg2 * tanhf(c2);
        hv.w = sg3 * tanhf(c3);
        *(float4*)(g_hs + (size_t)l * Bq * Hq + e0) = hv;

        gsync(target);   // h[l] visible before next phase A
    }
}

// ---------------- output projection + masking -------------------------------
// One warp per (b,l) output row. out row index = b*L + l.
__global__ __launch_bounds__(256) void out_kernel(
        const float* __restrict__ Wo,
        const float* __restrict__ bo,
        const int*   __restrict__ slen,
        float*       __restrict__ out) {
    __shared__ float woS[Hq * Oq];
    const int tid = threadIdx.x;
    for (int i = tid; i < Hq * Oq; i += 256) woS[i] = Wo[i];
    __syncthreads();

    const int warp = blockIdx.x * 8 + (tid >> 5);
    const int lane = tid & 31;
    const int b = warp >> 8;      // / L
    const int l = warp & (Lq - 1);

    const float* hrow = g_hs + ((size_t)l * Bq + b) * Hq;
    float a0 = 0.f, a1 = 0.f;
    for (int j = lane; j < Hq; j += 32) {
        float h = hrow[j];
        a0 += h * woS[j * 2];
        a1 += h * woS[j * 2 + 1];
    }
#pragma unroll
    for (int off = 16; off; off >>= 1) {
        a0 += __shfl_xor_sync(0xffffffffu, a0, off);
        a1 += __shfl_xor_sync(0xffffffffu, a1, off);
    }
    if (lane == 0) {
        float o0, o1;
        if (l <= slen[b]) {
            o0 = 1.f / (1.f + expf(-(a0 + bo[0])));
            o1 = 1.f / (1.f + expf(-(a1 + bo[1])));
        } else {
            o0 = 0.f;
            o1 = 1.f;
        }
        out[(size_t)warp * 2]     = o0;
        out[(size_t)warp * 2 + 1] = o1;
    }
}

// ---------------- launch ----------------------------------------------------
extern "C" void kernel_launch(void* const* d_in, const int* in_sizes, int n_in,
                              void* d_out, int out_size) {
    const float* x    = (const float*)d_in[0];
    const int*   slen = (const int*)  d_in[1];
    const float* Wh   = (const float*)d_in[2];
    const float* bh   = (const float*)d_in[3];
    const float* Wx   = (const float*)d_in[4];
    const float* bx   = (const float*)d_in[5];
    const float* Wo   = (const float*)d_in[6];
    const float* bo   = (const float*)d_in[7];
    float* out = (float*)d_out;

    init_bar_kernel<<<1, 1>>>();

    dim3 g1(Hq / 64, (Bq * Lq) / 64);       // (16, 512)
    xp_gemm_kernel<<<g1, 256>>>(x, Wx, bx);

    rnn_persist_kernel<<<NCTA, 256>>>(Wh, bh);

    out_kernel<<<(Bq * Lq) / 8, 256>>>(Wo, bo, slen, out);
}

// round 13
// speedup vs baseline: 1.0109x; 1.0075x over previous
#include <cuda_runtime.h>
#include <math.h>

#define Bq   128
#define Lq   256
#define Dq   512
#define Hq   1024
#define Oq   2
#define NCTA 128   // persistent recurrence grid

// ---------------- scratch (static device allocations; no cudaMalloc) --------
__device__ float g_xp[(size_t)Lq * Bq * Hq];   // (L, B, H)  128 MB
__device__ float g_hs[(size_t)Lq * Bq * Hq];   // (L, B, H)  128 MB
__device__ float g_zp[4 * Bq * Hq];            // split-K partials, 2 MB
__device__ unsigned g_count;
__device__ unsigned g_phase;

// ---------------- barrier init (reset every launch for graph replay) --------
__global__ void init_bar_kernel() {
    g_count = 0u;
    g_phase = 0u;
}

// ---------------- software grid barrier (all NCTA CTAs co-resident) ---------
__device__ __forceinline__ void gsync(unsigned &target) {
    __threadfence();          // make this thread's global writes visible
    __syncthreads();
    if (threadIdx.x == 0) {
        unsigned a = atomicAdd(&g_count, 1u);
        if (a == NCTA - 1) {
            g_count = 0u;
            __threadfence();
            atomicAdd(&g_phase, 1u);
        } else {
            while (*((volatile unsigned *)&g_phase) <= target) { /* spin */ }
        }
    }
    __syncthreads();
    target++;
}

// ---------------- xp = reshape(x) @ Wx + bx ---------------------------------
// Output row m = l*B + b  (time-major), A row = x[b][l][:]
// 64x64 tile, 4x4 micro-tile, 256 threads, KT=16.
__global__ __launch_bounds__(256) void xp_gemm_kernel(
        const float* __restrict__ x,
        const float* __restrict__ Wx,
        const float* __restrict__ bx) {
    __shared__ float aS[64][16];
    __shared__ float wS[16][64];

    const int tid = threadIdx.x;
    const int tx = tid & 15;        // j direction (4 cols each)
    const int ty = tid >> 4;        // m direction (4 rows each)
    const int m0 = blockIdx.y * 64;
    const int n0 = blockIdx.x * 64;

    // loader roles
    const int abb  = tid >> 2;            // 0..63  (row in tile)
    const int akk4 = (tid & 3) * 4;       // 0,4,8,12
    const int wkk  = tid >> 4;            // 0..15
    const int wjj  = (tid & 15) * 4;      // 0..60

    const int m = m0 + abb;
    // x is (B, L, D): offset of row m: b = m%128, l = m/128
    const float* arow = x + ((size_t)(m & (Bq - 1)) * Lq + (m >> 7)) * Dq;

    float acc[4][4] = {};

    for (int k0 = 0; k0 < Dq; k0 += 16) {
        float4 av = *(const float4*)(arow + k0 + akk4);
        *(float4*)&aS[abb][akk4] = av;
        float4 wv = *(const float4*)(Wx + (size_t)(k0 + wkk) * Hq + n0 + wjj);
        *(float4*)&wS[wkk][wjj] = wv;
        __syncthreads();
#pragma unroll
        for (int kk = 0; kk < 16; kk++) {
            float4 w4 = *(float4*)&wS[kk][tx * 4];
            float av4[4];
#pragma unroll
            for (int i = 0; i < 4; i++) av4[i] = aS[ty * 4 + i][kk];
#pragma unroll
            for (int i = 0; i < 4; i++) {
                acc[i][0] += av4[i] * w4.x;
                acc[i][1] += av4[i] * w4.y;
                acc[i][2] += av4[i] * w4.z;
                acc[i][3] += av4[i] * w4.w;
            }
        }
        __syncthreads();
    }

    const int j = n0 + tx * 4;
    float4 bxv = *(const float4*)(bx + j);
#pragma unroll
    for (int i = 0; i < 4; i++) {
        int mm = m0 + ty * 4 + i;
        float4 o;
        o.x = acc[i][0] + bxv.x;
        o.y = acc[i][1] + bxv.y;
        o.z = acc[i][2] + bxv.z;
        o.w = acc[i][3] + bxv.w;
        *(float4*)(g_xp + (size_t)mm * Hq + j) = o;
    }
}

// ---------------- persistent recurrence kernel ------------------------------
// 128 CTAs x 256 threads.
// Phase A (l>0): split-K GEMM partials  z_part = h[l-1] @ Wh
//   CTA (ks, bt, jt): b-tile 64, j-tile 64, k-range 256. 4x4 micro-tiles.
// Phase B: CTA c owns b-row c (1024 j). thread owns j = tid*4..+3, c in regs.
__global__ __launch_bounds__(256) void rnn_persist_kernel(
        const float* __restrict__ Wh,
        const float* __restrict__ bh) {
    const int tid = threadIdx.x;
    const int cta = blockIdx.x;
    const int ks  = cta >> 5;            // 0..3
    const int rem = cta & 31;
    const int bt  = rem >> 4;            // 0..1
    const int jt  = rem & 15;            // 0..15
    const int b0  = bt * 64;
    const int j0  = jt * 64;
    const int kbase = ks * 256;

    const int tx = tid & 15;
    const int ty = tid >> 4;

    __shared__ float hS[64][16];
    __shared__ float wS[16][64];

    // loader roles (phase A)
    const int hbb  = tid >> 2;
    const int hkk4 = (tid & 3) * 4;
    const int wkk  = tid >> 4;
    const int wjj  = (tid & 15) * 4;

    // phase B ownership: element range e0..e0+3 of the (B*H) state
    const size_t e0 = ((size_t)cta * 256 + tid) * 4;   // b = cta, j = tid*4
    float4 bhv = *(const float4*)(bh + (tid * 4));
    float c0 = 0.f, c1 = 0.f, c2 = 0.f, c3 = 0.f;

    unsigned target = 0;

    for (int l = 0; l < Lq; l++) {
        float zs0 = 0.f, zs1 = 0.f, zs2 = 0.f, zs3 = 0.f;
        if (l > 0) {
            // ---------------- phase A ----------------
            float acc[4][4] = {};
            const float* hprev = g_hs + (size_t)(l - 1) * Bq * Hq;
            for (int kc = 0; kc < 256; kc += 16) {
                const int k0 = kbase + kc;
                float4 hv = __ldcg((const float4*)(hprev +
                                   (size_t)(b0 + hbb) * Hq + k0 + hkk4));
                *(float4*)&hS[hbb][hkk4] = hv;
                float4 wv = *(const float4*)(Wh +
                                   (size_t)(k0 + wkk) * Hq + j0 + wjj);
                *(float4*)&wS[wkk][wjj] = wv;
                __syncthreads();
#pragma unroll
                for (int kk = 0; kk < 16; kk++) {
                    float4 w4 = *(float4*)&wS[kk][tx * 4];
                    float av4[4];
#pragma unroll
                    for (int i = 0; i < 4; i++) av4[i] = hS[ty * 4 + i][kk];
#pragma unroll
                    for (int i = 0; i < 4; i++) {
                        acc[i][0] += av4[i] * w4.x;
                        acc[i][1] += av4[i] * w4.y;
                        acc[i][2] += av4[i] * w4.z;
                        acc[i][3] += av4[i] * w4.w;
                    }
                }
                __syncthreads();
            }
            // write partials
            float* zp = g_zp + (size_t)ks * Bq * Hq;
#pragma unroll
            for (int i = 0; i < 4; i++) {
                float4 o = make_float4(acc[i][0], acc[i][1], acc[i][2], acc[i][3]);
                *(float4*)(zp + (size_t)(b0 + ty * 4 + i) * Hq + j0 + tx * 4) = o;
            }
            gsync(target);   // partials visible to everyone

            // ---------------- phase B: reduce partials ----------------
            float4 p0 = __ldcg((const float4*)(g_zp + e0));
            float4 p1 = __ldcg((const float4*)(g_zp + (size_t)Bq * Hq + e0));
            float4 p2 = __ldcg((const float4*)(g_zp + (size_t)2 * Bq * Hq + e0));
            float4 p3 = __ldcg((const float4*)(g_zp + (size_t)3 * Bq * Hq + e0));
            zs0 = p0.x + p1.x + p2.x + p3.x;
            zs1 = p0.y + p1.y + p2.y + p3.y;
            zs2 = p0.z + p1.z + p2.z + p3.z;
            zs3 = p0.w + p1.w + p2.w + p3.w;
        }

        float4 xpv = __ldcg((const float4*)(g_xp + (size_t)l * Bq * Hq + e0));
        float z0 = zs0 + bhv.x + xpv.x;
        float z1 = zs1 + bhv.y + xpv.y;
        float z2 = zs2 + bhv.z + xpv.z;
        float z3 = zs3 + bhv.w + xpv.w;

        float sg0 = 1.f / (1.f + expf(-z0));
        float sg1 = 1.f / (1.f + expf(-z1));
        float sg2 = 1.f / (1.f + expf(-z2));
        float sg3 = 1.f / (1.f + expf(-z3));
        float g0 = tanhf(z0), g1 = tanhf(z1), g2 = tanhf(z2), g3 = tanhf(z3);
        c0 = sg0 * (c0 + g0);
        c1 = sg1 * (c1 + g1);
        c2 = sg2 * (c2 + g2);
        c3 = sg3 * (c3 + g3);
        float4 hv;
        hv.x = sg0 * tanhf(c0);
        hv.y = sg1 * tanhf(c1);
        hv.z = sg2 * tanhf(c2);
        hv.w = sg3 * tanhf(c3);
        *(float4*)(g_hs + (size_t)l * Bq * Hq + e0) = hv;

        gsync(target);   // h[l] visible before next phase A
    }
}

// ---------------- output projection + masking -------------------------------
// One warp per (b,l) output row. out row index = b*L + l.
__global__ __launch_bounds__(256) void out_kernel(
        const float* __restrict__ Wo,
        const float* __restrict__ bo,
        const int*   __restrict__ slen,
        float*       __restrict__ out) {
    __shared__ float woS[Hq * Oq];
    const int tid = threadIdx.x;
    for (int i = tid; i < Hq * Oq; i += 256) woS[i] = Wo[i];
    __syncthreads();

    const int warp = blockIdx.x * 8 + (tid >> 5);
    const int lane = tid & 31;
    const int b = warp >> 8;      // / L
    const int l = warp & (Lq - 1);

    const float* hrow = g_hs + ((size_t)l * Bq + b) * Hq;
    float a0 = 0.f, a1 = 0.f;
    for (int j = lane; j < Hq; j += 32) {
        float h = hrow[j];
        a0 += h * woS[j * 2];
        a1 += h * woS[j * 2 + 1];
    }
#pragma unroll
    for (int off = 16; off; off >>= 1) {
        a0 += __shfl_xor_sync(0xffffffffu, a0, off);
        a1 += __shfl_xor_sync(0xffffffffu, a1, off);
    }
    if (lane == 0) {
        float o0, o1;
        if (l <= slen[b]) {
            o0 = 1.f / (1.f + expf(-(a0 + bo[0])));
            o1 = 1.f / (1.f + expf(-(a1 + bo[1])));
        } else {
            o0 = 0.f;
            o1 = 1.f;
        }
        out[(size_t)warp * 2]     = o0;
        out[(size_t)warp * 2 + 1] = o1;
    }
}

// ---------------- launch ----------------------------------------------------
extern "C" void kernel_launch(void* const* d_in, const int* in_sizes, int n_in,
                              void* d_out, int out_size) {
    const float* x    = (const float*)d_in[0];
    const int*   slen = (const int*)  d_in[1];
    const float* Wh   = (const float*)d_in[2];
    const float* bh   = (const float*)d_in[3];
    const float* Wx   = (const float*)d_in[4];
    const float* bx   = (const float*)d_in[5];
    const float* Wo   = (const float*)d_in[6];
    const float* bo   = (const float*)d_in[7];
    float* out = (float*)d_out;

    init_bar_kernel<<<1, 1>>>();

    dim3 g1(Hq / 64, (Bq * Lq) / 64);       // (16, 512)
    xp_gemm_kernel<<<g1, 256>>>(x, Wx, bx);

    rnn_persist_kernel<<<NCTA, 256>>>(Wh, bh);

    out_kernel<<<(Bq * Lq) / 8, 256>>>(Wo, bo, slen, out);
}